// round 7
// baseline (speedup 1.0000x reference)
#include <cuda_runtime.h>
#include <cuda_bf16.h>
#include <cuda_fp16.h>
#include <cstdint>

// Problem constants
#define N_ENT    100000
#define N_REL    250000
#define N_TRIG   50000
#define N_ARGS   250000
#define ENT_DIM  288
#define REL_R    256
#define RTYPE_DIM 32
#define ROLE_DIM 256
#define ARG_DIM  576
#define KDIM     1152          // 2 * ARG_DIM (in-slot | out-slot)
#define OUT_COLS 544           // ENT_DIM + ROLE_DIM

// Scratch (fp16 X accumulators + fp16 W^T)
__device__ __half g_Xh[(size_t)N_TRIG * KDIM];   // 115.2 MB
__device__ __half g_Bth[ROLE_DIM * KDIM];        // W^T [n][k], fp16

// ---------------------------------------------------------------------------
// helpers
// ---------------------------------------------------------------------------
__device__ __forceinline__ uint32_t smem_u32(const void* p) {
    uint32_t a;
    asm("{ .reg .u64 t; cvta.to.shared.u64 t, %1; cvt.u32.u64 %0, t; }"
        : "=r"(a) : "l"(p));
    return a;
}

__device__ __forceinline__ void red_h8(__half* p, uint32_t a, uint32_t b,
                                       uint32_t c, uint32_t d) {
    asm volatile("red.global.add.noftz.v4.f16x2 [%0], {%1,%2,%3,%4};"
                 :: "l"(p), "r"(a), "r"(b), "r"(c), "r"(d) : "memory");
}

__device__ __forceinline__ void cp16(uint32_t dst, const void* src) {
    asm volatile("cp.async.cg.shared.global [%0], [%1], 16;" :: "r"(dst), "l"(src));
}
__device__ __forceinline__ void cp16_pred(uint32_t dst, const void* src, int bytes) {
    asm volatile("cp.async.cg.shared.global [%0], [%1], 16, %2;"
                 :: "r"(dst), "l"(src), "r"(bytes));
}
__device__ __forceinline__ void cp_commit() {
    asm volatile("cp.async.commit_group;" ::: "memory");
}
template <int N> __device__ __forceinline__ void cp_wait() {
    asm volatile("cp.async.wait_group %0;" :: "n"(N) : "memory");
}

#define MMA_F16(acc, ar, br)                                                    \
    asm volatile(                                                               \
        "mma.sync.aligned.m16n8k16.row.col.f32.f16.f16.f32 "                    \
        "{%0,%1,%2,%3},{%4,%5,%6,%7},{%8,%9},{%0,%1,%2,%3};"                    \
        : "+f"((acc)[0]), "+f"((acc)[1]), "+f"((acc)[2]), "+f"((acc)[3])        \
        : "r"((ar)[0]), "r"((ar)[1]), "r"((ar)[2]), "r"((ar)[3]),               \
          "r"((br)[0]), "r"((br)[1]))

#define LDMATRIX_X4(r, addr)                                                    \
    asm volatile("ldmatrix.sync.aligned.m8n8.x4.shared.b16 {%0,%1,%2,%3}, [%4];"\
                 : "=r"((r)[0]), "=r"((r)[1]), "=r"((r)[2]), "=r"((r)[3])       \
                 : "r"(addr))

#define LDMATRIX_X2(r, addr)                                                    \
    asm volatile("ldmatrix.sync.aligned.m8n8.x2.shared.b16 {%0,%1}, [%2];"      \
                 : "=r"((r)[0]), "=r"((r)[1]) : "r"(addr))

// ---------------------------------------------------------------------------
// Fused prep kernel: [bprep | scatter | trig_copy] by block range.
// All three are independent; fusing overlaps the small streaming jobs with
// the DRAM-bound gather/scatter.
// ---------------------------------------------------------------------------
#define PREP_BPREP 1152                     // (1152*256 elems)/256 thr
#define PREP_SCAT  (N_ARGS / 8)             // 31250, 1 arg per warp
#define PREP_TRIG  (N_TRIG / 8)             // 6250, 1 trig per warp
#define PREP_GRID  (PREP_BPREP + PREP_SCAT + PREP_TRIG)

__global__ __launch_bounds__(256)
void prep_kernel(const float* __restrict__ ent_embeds,
                 const float* __restrict__ rel_embeds,
                 const float* __restrict__ rtype_table,
                 const float* __restrict__ Win,
                 const float* __restrict__ Wout,
                 const int*   __restrict__ rtype_ids,
                 const int*   __restrict__ trig_ent_id,
                 const int*   __restrict__ arg_trig,
                 const int*   __restrict__ arg_rel,
                 const int*   __restrict__ arg_ent,
                 const int*   __restrict__ arg_is_in,
                 float* __restrict__ out) {
    int bid = blockIdx.x;
    int tid = threadIdx.x;
    int lane = tid & 31;
    int wip = tid >> 5;

    if (bid < PREP_BPREP) {
        // ---- W transpose -> fp16 ----
        int idx = bid * 256 + tid;
        int k = idx / ROLE_DIM;
        int n = idx % ROLE_DIM;
        float v = (k < ARG_DIM) ? Win[k * ROLE_DIM + n]
                                : Wout[(k - ARG_DIM) * ROLE_DIM + n];
        g_Bth[n * KDIM + k] = __float2half_rn(v);
        return;
    }
    bid -= PREP_BPREP;
    if (bid < PREP_SCAT) {
        // ---- scatter: one warp per argument ----
        int warp = bid * 8 + wip;
        int r = arg_rel[warp];
        int e = arg_ent[warp];
        int t = arg_trig[warp];
        int m = arg_is_in[warp];
        int rt = rtype_ids[r];

        const float4* relv = (const float4*)(rel_embeds  + (size_t)r  * REL_R);
        const float4* rtv  = (const float4*)(rtype_table + (size_t)rt * RTYPE_DIM);
        const float4* entv = (const float4*)(ent_embeds  + (size_t)e  * ENT_DIM);
        __half* base = g_Xh + (size_t)t * KDIM + (m ? 0 : ARG_DIM);

        #pragma unroll
        for (int it = 0; it < 3; ++it) {
            int c = lane + it * 32;          // 8-float chunk (0..71)
            if (c >= 72) break;
            float4 v0, v1;
            if (c < 32)       { v0 = relv[c * 2];        v1 = relv[c * 2 + 1]; }
            else if (c < 36)  { v0 = rtv[(c - 32) * 2];  v1 = rtv[(c - 32) * 2 + 1]; }
            else              { v0 = entv[(c - 36) * 2]; v1 = entv[(c - 36) * 2 + 1]; }
            __half2 h0 = __floats2half2_rn(v0.x, v0.y);
            __half2 h1 = __floats2half2_rn(v0.z, v0.w);
            __half2 h2 = __floats2half2_rn(v1.x, v1.y);
            __half2 h3 = __floats2half2_rn(v1.z, v1.w);
            red_h8(base + c * 8, *(uint32_t*)&h0, *(uint32_t*)&h1,
                   *(uint32_t*)&h2, *(uint32_t*)&h3);
        }
        return;
    }
    bid -= PREP_SCAT;
    {
        // ---- trig copy: one warp per trigger ----
        int warp = bid * 8 + wip;
        const float4* src = (const float4*)(ent_embeds + (size_t)trig_ent_id[warp] * ENT_DIM);
        float4* dst = (float4*)(out + (size_t)warp * OUT_COLS);
        #pragma unroll
        for (int it = 0; it < 3; ++it) {
            int c = lane + it * 32;
            if (c < ENT_DIM / 4) dst[c] = src[c];
        }
    }
}

// ---------------------------------------------------------------------------
// mma.sync fp16 GEMM: out[:,288:544] = Xh[50000,1152] @ Wcat
// CTA tile 128x128, K-chunk 64, 3-stage cp.async pipeline,
// intra-chunk fragment double-buffering. Rows padded to 144 B (conflict-free
// ldmatrix: 144*r mod 128 walks all 16B columns over 8 rows).
// grid = (2, 391): n-major so the 2 CTAs sharing an m-tile co-run (A hits L2).
// ---------------------------------------------------------------------------
#define CHUNK  64
#define NCH    (KDIM / CHUNK)     // 18
#define ROWB   144
#define OFF_B  (128 * ROWB)       // 18432
#define STG_STRIDE (2 * 128 * ROWB)   // 36864
#define NSTAGE 3
#define GSMEM  (NSTAGE * STG_STRIDE)  // 110592

__global__ __launch_bounds__(256, 2)
void gemm_mma_kernel(float* __restrict__ out) {
    extern __shared__ char sm[];
    const uint32_t smb = smem_u32(sm);
    const int tid = threadIdx.x;
    const int lid = tid & 31;
    const int wid = tid >> 5;
    const int m0 = blockIdx.y * 128;
    const int n0 = blockIdx.x * 128;
    const int wm = (wid >> 2) * 64;        // warp m offset (0 or 64)
    const int wn = (wid & 3) * 32;         // warp n offset (0,32,64,96)
    const int g  = lid >> 2;               // 0..7
    const int kp = (lid & 3) * 2;          // 0,2,4,6

    float acc[4][4][4];
    #pragma unroll
    for (int a = 0; a < 4; a++)
        #pragma unroll
        for (int b = 0; b < 4; b++)
            #pragma unroll
            for (int c = 0; c < 4; c++) acc[a][b][c] = 0.f;

    auto cpStage = [&](int c, int p) {
        uint32_t stg = smb + p * STG_STRIDE;
        #pragma unroll
        for (int u = 0; u < 4; u++) {
            int idx = tid * 4 + u;           // 0..1023
            int row = idx >> 3, seg = idx & 7;
            int gm = m0 + row;
            const __half* sa = g_Xh + (size_t)gm * KDIM + c * CHUNK + seg * 8;
            cp16_pred(stg + row * ROWB + seg * 16, sa, (gm < N_TRIG) ? 16 : 0);
            const __half* sb = g_Bth + (size_t)(n0 + row) * KDIM + c * CHUNK + seg * 8;
            cp16(stg + OFF_B + row * ROWB + seg * 16, sb);
        }
        cp_commit();
    };

    // fragment loads for k-step ks (0..3) of stage base
    auto ldA = [&](uint32_t base, int ks, uint32_t (*a)[4]) {
        #pragma unroll
        for (int mf = 0; mf < 4; mf++) {
            uint32_t addr = base + (uint32_t)(wm + mf * 16 + (lid & 15)) * ROWB
                          + ks * 32 + (lid >> 4) * 16;
            LDMATRIX_X4(a[mf], addr);
        }
    };
    auto ldB = [&](uint32_t base, int ks, uint32_t (*b)[2]) {
        #pragma unroll
        for (int nf = 0; nf < 4; nf++) {
            uint32_t addr = base + OFF_B + (uint32_t)(wn + nf * 8 + (lid & 7)) * ROWB
                          + ks * 32 + ((lid >> 3) & 1) * 16;
            LDMATRIX_X2(b[nf], addr);
        }
    };

    auto compute = [&](int p) {
        const uint32_t base = smb + p * STG_STRIDE;
        uint32_t a[2][4][4], b[2][4][2];
        ldA(base, 0, a[0]);
        ldB(base, 0, b[0]);
        #pragma unroll
        for (int ks = 0; ks < 4; ks++) {
            int cur = ks & 1, nxt = cur ^ 1;
            if (ks < 3) { ldA(base, ks + 1, a[nxt]); ldB(base, ks + 1, b[nxt]); }
            #pragma unroll
            for (int nf = 0; nf < 4; nf++)
                #pragma unroll
                for (int mf = 0; mf < 4; mf++)
                    MMA_F16(acc[mf][nf], a[cur][mf], b[cur][nf]);
        }
    };

    // ---- prologue: stages 0,1 in flight ----
    cpStage(0, 0);
    cpStage(1, 1);

    // ---- mainloop ----
    for (int i = 0; i < NCH; i++) {
        cp_wait<1>();
        __syncthreads();
        if (i + 2 < NCH) cpStage(i + 2, (i + 2) % NSTAGE);
        else             cp_commit();           // keep group count uniform
        compute(i % NSTAGE);
    }

    // ---- epilogue ----
    #pragma unroll
    for (int mf = 0; mf < 4; mf++) {
        int r = m0 + wm + mf * 16 + g;
        #pragma unroll
        for (int nf = 0; nf < 4; nf++) {
            int cc = ENT_DIM + n0 + wn + nf * 8 + kp;
            if (r < N_TRIG)
                *(float2*)(out + (size_t)r * OUT_COLS + cc) =
                    make_float2(acc[mf][nf][0], acc[mf][nf][1]);
            if (r + 8 < N_TRIG)
                *(float2*)(out + (size_t)(r + 8) * OUT_COLS + cc) =
                    make_float2(acc[mf][nf][2], acc[mf][nf][3]);
        }
    }
}

// ---------------------------------------------------------------------------
// Launch
// ---------------------------------------------------------------------------
extern "C" void kernel_launch(void* const* d_in, const int* in_sizes, int n_in,
                              void* d_out, int out_size) {
    const float* ent_embeds  = (const float*)d_in[0];
    const float* rel_embeds  = (const float*)d_in[1];
    const float* rtype_table = (const float*)d_in[2];
    const float* W_in        = (const float*)d_in[3];
    const float* W_out       = (const float*)d_in[4];
    const int*   rtype_ids   = (const int*)d_in[5];
    const int*   trig_ent_id = (const int*)d_in[6];
    const int*   arg_trig    = (const int*)d_in[7];
    const int*   arg_rel     = (const int*)d_in[8];
    const int*   arg_ent     = (const int*)d_in[9];
    const int*   arg_is_in   = (const int*)d_in[10];
    float* out = (float*)d_out;

    cudaFuncSetAttribute(gemm_mma_kernel,
                         cudaFuncAttributeMaxDynamicSharedMemorySize, GSMEM);

    // zero fp16 X accumulator (115 MB)
    void* xptr = nullptr;
    cudaGetSymbolAddress(&xptr, g_Xh);
    cudaMemsetAsync(xptr, 0, (size_t)N_TRIG * KDIM * sizeof(__half), 0);

    // fused: W transpose + scatter + trigger-embedding copy
    prep_kernel<<<PREP_GRID, 256>>>(ent_embeds, rel_embeds, rtype_table,
                                    W_in, W_out, rtype_ids, trig_ent_id,
                                    arg_trig, arg_rel, arg_ent, arg_is_in, out);

    // tensor-core GEMM -> out[:, 288:544]
    dim3 grid(ROLE_DIM / 128, (N_TRIG + 127) / 128);
    gemm_mma_kernel<<<grid, 256, GSMEM>>>(out);
}

// round 8
// speedup vs baseline: 1.1172x; 1.1172x over previous
#include <cuda_runtime.h>
#include <cuda_bf16.h>
#include <cuda_fp16.h>
#include <cstdint>

// Problem constants
#define N_ENT    100000
#define N_REL    250000
#define N_TRIG   50000
#define N_ARGS   250000
#define ENT_DIM  288
#define REL_R    256
#define RTYPE_DIM 32
#define ROLE_DIM 256
#define ARG_DIM  576
#define KDIM     1152          // 2 * ARG_DIM (in-slot | out-slot)
#define OUT_COLS 544           // ENT_DIM + ROLE_DIM

// Scratch (fp16 X accumulators + fp16 W^T)
__device__ __half g_Xh[(size_t)N_TRIG * KDIM];   // 115.2 MB
__device__ __half g_Bth[ROLE_DIM * KDIM];        // W^T [n][k], fp16

// ---------------------------------------------------------------------------
// helpers
// ---------------------------------------------------------------------------
__device__ __forceinline__ uint32_t smem_u32(const void* p) {
    uint32_t a;
    asm("{ .reg .u64 t; cvta.to.shared.u64 t, %1; cvt.u32.u64 %0, t; }"
        : "=r"(a) : "l"(p));
    return a;
}

__device__ __forceinline__ void red_h8(__half* p, uint32_t a, uint32_t b,
                                       uint32_t c, uint32_t d) {
    asm volatile("red.global.add.noftz.v4.f16x2 [%0], {%1,%2,%3,%4};"
                 :: "l"(p), "r"(a), "r"(b), "r"(c), "r"(d) : "memory");
}

__device__ __forceinline__ void cp16(uint32_t dst, const void* src) {
    asm volatile("cp.async.cg.shared.global [%0], [%1], 16;" :: "r"(dst), "l"(src));
}
__device__ __forceinline__ void cp16_pred(uint32_t dst, const void* src, int bytes) {
    asm volatile("cp.async.cg.shared.global [%0], [%1], 16, %2;"
                 :: "r"(dst), "l"(src), "r"(bytes));
}
__device__ __forceinline__ void cp_commit() {
    asm volatile("cp.async.commit_group;" ::: "memory");
}
template <int N> __device__ __forceinline__ void cp_wait() {
    asm volatile("cp.async.wait_group %0;" :: "n"(N) : "memory");
}

#define MMA_F16(acc, ar, br)                                                    \
    asm volatile(                                                               \
        "mma.sync.aligned.m16n8k16.row.col.f32.f16.f16.f32 "                    \
        "{%0,%1,%2,%3},{%4,%5,%6,%7},{%8,%9},{%0,%1,%2,%3};"                    \
        : "+f"((acc)[0]), "+f"((acc)[1]), "+f"((acc)[2]), "+f"((acc)[3])        \
        : "r"((ar)[0]), "r"((ar)[1]), "r"((ar)[2]), "r"((ar)[3]),               \
          "r"((br)[0]), "r"((br)[1]))

#define LDMATRIX_X4(r, addr)                                                    \
    asm volatile("ldmatrix.sync.aligned.m8n8.x4.shared.b16 {%0,%1,%2,%3}, [%4];"\
                 : "=r"((r)[0]), "=r"((r)[1]), "=r"((r)[2]), "=r"((r)[3])       \
                 : "r"(addr))

// ---------------------------------------------------------------------------
// Fused prep kernel: [bprep | scatter | trig_copy] by block range.
// ---------------------------------------------------------------------------
#define PREP_BPREP 1152                     // (1152*256 elems)/256 thr
#define PREP_SCAT  (N_ARGS / 8)             // 31250, 1 arg per warp
#define PREP_TRIG  (N_TRIG / 8)             // 6250, 1 trig per warp
#define PREP_GRID  (PREP_BPREP + PREP_SCAT + PREP_TRIG)

__global__ __launch_bounds__(256)
void prep_kernel(const float* __restrict__ ent_embeds,
                 const float* __restrict__ rel_embeds,
                 const float* __restrict__ rtype_table,
                 const float* __restrict__ Win,
                 const float* __restrict__ Wout,
                 const int*   __restrict__ rtype_ids,
                 const int*   __restrict__ trig_ent_id,
                 const int*   __restrict__ arg_trig,
                 const int*   __restrict__ arg_rel,
                 const int*   __restrict__ arg_ent,
                 const int*   __restrict__ arg_is_in,
                 float* __restrict__ out) {
    int bid = blockIdx.x;
    int tid = threadIdx.x;
    int lane = tid & 31;
    int wip = tid >> 5;

    if (bid < PREP_BPREP) {
        int idx = bid * 256 + tid;
        int k = idx / ROLE_DIM;
        int n = idx % ROLE_DIM;
        float v = (k < ARG_DIM) ? Win[k * ROLE_DIM + n]
                                : Wout[(k - ARG_DIM) * ROLE_DIM + n];
        g_Bth[n * KDIM + k] = __float2half_rn(v);
        return;
    }
    bid -= PREP_BPREP;
    if (bid < PREP_SCAT) {
        int warp = bid * 8 + wip;
        int r = arg_rel[warp];
        int e = arg_ent[warp];
        int t = arg_trig[warp];
        int m = arg_is_in[warp];
        int rt = rtype_ids[r];

        const float4* relv = (const float4*)(rel_embeds  + (size_t)r  * REL_R);
        const float4* rtv  = (const float4*)(rtype_table + (size_t)rt * RTYPE_DIM);
        const float4* entv = (const float4*)(ent_embeds  + (size_t)e  * ENT_DIM);
        __half* base = g_Xh + (size_t)t * KDIM + (m ? 0 : ARG_DIM);

        #pragma unroll
        for (int it = 0; it < 3; ++it) {
            int c = lane + it * 32;          // 8-float chunk (0..71)
            if (c >= 72) break;
            float4 v0, v1;
            if (c < 32)       { v0 = relv[c * 2];        v1 = relv[c * 2 + 1]; }
            else if (c < 36)  { v0 = rtv[(c - 32) * 2];  v1 = rtv[(c - 32) * 2 + 1]; }
            else              { v0 = entv[(c - 36) * 2]; v1 = entv[(c - 36) * 2 + 1]; }
            __half2 h0 = __floats2half2_rn(v0.x, v0.y);
            __half2 h1 = __floats2half2_rn(v0.z, v0.w);
            __half2 h2 = __floats2half2_rn(v1.x, v1.y);
            __half2 h3 = __floats2half2_rn(v1.z, v1.w);
            red_h8(base + c * 8, *(uint32_t*)&h0, *(uint32_t*)&h1,
                   *(uint32_t*)&h2, *(uint32_t*)&h3);
        }
        return;
    }
    bid -= PREP_SCAT;
    {
        int warp = bid * 8 + wip;
        const float4* src = (const float4*)(ent_embeds + (size_t)trig_ent_id[warp] * ENT_DIM);
        float4* dst = (float4*)(out + (size_t)warp * OUT_COLS);
        #pragma unroll
        for (int it = 0; it < 3; ++it) {
            int c = lane + it * 32;
            if (c < ENT_DIM / 4) dst[c] = src[c];
        }
    }
}

// ---------------------------------------------------------------------------
// mma.sync fp16 GEMM: out[:,288:544] = Xh[50000,1152] @ Wcat
// CTA: 128 threads (4 warps), tile 128m x 128n, warp tile 64x64.
// K-chunk 64, 3-stage cp.async pipeline. Rows padded to 144 B (16B/row bank
// walk -> conflict-free ldmatrix). grid n-major so m-tile pairs co-run.
// Per warp per k16-step: 8 ldmatrix.x4 -> 32 MMAs (0.25 aux ops/MMA).
// ---------------------------------------------------------------------------
#define CHUNK  64
#define NCH    (KDIM / CHUNK)         // 18
#define ROWB   144
#define OFF_B  (128 * ROWB)           // 18432
#define STG_STRIDE (2 * 128 * ROWB)   // 36864
#define NSTAGE 3
#define GSMEM  (NSTAGE * STG_STRIDE)  // 110592

__global__ __launch_bounds__(128, 2)
void gemm_mma_kernel(float* __restrict__ out) {
    extern __shared__ char sm[];
    const uint32_t smb = smem_u32(sm);
    const int tid = threadIdx.x;
    const int lid = tid & 31;
    const int wid = tid >> 5;
    const int m0 = blockIdx.y * 128;
    const int n0 = blockIdx.x * 128;
    const int wm = (wid >> 1) * 64;        // warp m offset (0 or 64)
    const int wn = (wid & 1) * 64;         // warp n offset (0 or 64)
    const int g  = lid >> 2;               // 0..7
    const int kp = (lid & 3) * 2;          // 0,2,4,6

    float acc[4][8][4];                    // mf x nf x frag
    #pragma unroll
    for (int a = 0; a < 4; a++)
        #pragma unroll
        for (int b = 0; b < 8; b++)
            #pragma unroll
            for (int c = 0; c < 4; c++) acc[a][b][c] = 0.f;

    auto cpStage = [&](int c, int p) {
        uint32_t stg = smb + p * STG_STRIDE;
        #pragma unroll
        for (int u = 0; u < 8; u++) {
            int idx = u * 128 + tid;         // 0..1023
            int row = idx >> 3, seg = idx & 7;
            int gm = m0 + row;
            const __half* sa = g_Xh + (size_t)gm * KDIM + c * CHUNK + seg * 8;
            cp16_pred(stg + row * ROWB + seg * 16, sa, (gm < N_TRIG) ? 16 : 0);
            const __half* sb = g_Bth + (size_t)(n0 + row) * KDIM + c * CHUNK + seg * 8;
            cp16(stg + OFF_B + row * ROWB + seg * 16, sb);
        }
        cp_commit();
    };

    auto compute = [&](int p) {
        const uint32_t base = smb + p * STG_STRIDE;
        #pragma unroll
        for (int ks = 0; ks < 4; ks++) {
            // A fragments: 4 x ldmatrix.x4 (16m x 16k tiles)
            uint32_t a[4][4];
            #pragma unroll
            for (int mf = 0; mf < 4; mf++) {
                uint32_t addr = base + (uint32_t)(wm + mf * 16 + (lid & 15)) * ROWB
                              + ks * 32 + (lid >> 4) * 16;
                LDMATRIX_X4(a[mf], addr);
            }
            // B fragments: 4 x ldmatrix.x4, each covers TWO n8 frags (16n x 16k)
            uint32_t b[4][4];
            #pragma unroll
            for (int np = 0; np < 4; np++) {
                uint32_t addr = base + OFF_B + (uint32_t)(wn + np * 16 + (lid & 15)) * ROWB
                              + ks * 32 + (lid >> 4) * 16;
                LDMATRIX_X4(b[np], addr);
            }
            // 32 MMAs
            #pragma unroll
            for (int np = 0; np < 4; np++) {
                uint32_t blo[2] = { b[np][0], b[np][2] };   // n rows 0-7 of pair
                uint32_t bhi[2] = { b[np][1], b[np][3] };   // n rows 8-15
                #pragma unroll
                for (int mf = 0; mf < 4; mf++) {
                    MMA_F16(acc[mf][2 * np],     a[mf], blo);
                    MMA_F16(acc[mf][2 * np + 1], a[mf], bhi);
                }
            }
        }
    };

    // ---- prologue: stages 0,1 in flight ----
    cpStage(0, 0);
    cpStage(1, 1);

    // ---- mainloop ----
    for (int i = 0; i < NCH; i++) {
        cp_wait<1>();
        __syncthreads();
        if (i + 2 < NCH) cpStage(i + 2, (i + 2) % NSTAGE);
        else             cp_commit();           // keep group count uniform
        compute(i % NSTAGE);
        __syncthreads();
    }

    // ---- epilogue ----
    #pragma unroll
    for (int mf = 0; mf < 4; mf++) {
        int r = m0 + wm + mf * 16 + g;
        #pragma unroll
        for (int nf = 0; nf < 8; nf++) {
            int cc = ENT_DIM + n0 + wn + nf * 8 + kp;
            if (r < N_TRIG)
                *(float2*)(out + (size_t)r * OUT_COLS + cc) =
                    make_float2(acc[mf][nf][0], acc[mf][nf][1]);
            if (r + 8 < N_TRIG)
                *(float2*)(out + (size_t)(r + 8) * OUT_COLS + cc) =
                    make_float2(acc[mf][nf][2], acc[mf][nf][3]);
        }
    }
}

// ---------------------------------------------------------------------------
// Launch
// ---------------------------------------------------------------------------
extern "C" void kernel_launch(void* const* d_in, const int* in_sizes, int n_in,
                              void* d_out, int out_size) {
    const float* ent_embeds  = (const float*)d_in[0];
    const float* rel_embeds  = (const float*)d_in[1];
    const float* rtype_table = (const float*)d_in[2];
    const float* W_in        = (const float*)d_in[3];
    const float* W_out       = (const float*)d_in[4];
    const int*   rtype_ids   = (const int*)d_in[5];
    const int*   trig_ent_id = (const int*)d_in[6];
    const int*   arg_trig    = (const int*)d_in[7];
    const int*   arg_rel     = (const int*)d_in[8];
    const int*   arg_ent     = (const int*)d_in[9];
    const int*   arg_is_in   = (const int*)d_in[10];
    float* out = (float*)d_out;

    cudaFuncSetAttribute(gemm_mma_kernel,
                         cudaFuncAttributeMaxDynamicSharedMemorySize, GSMEM);

    // zero fp16 X accumulator (115 MB)
    void* xptr = nullptr;
    cudaGetSymbolAddress(&xptr, g_Xh);
    cudaMemsetAsync(xptr, 0, (size_t)N_TRIG * KDIM * sizeof(__half), 0);

    // fused: W transpose + scatter + trigger-embedding copy
    prep_kernel<<<PREP_GRID, 256>>>(ent_embeds, rel_embeds, rtype_table,
                                    W_in, W_out, rtype_ids, trig_ent_id,
                                    arg_trig, arg_rel, arg_ent, arg_is_in, out);

    // tensor-core GEMM -> out[:, 288:544]
    dim3 grid(ROLE_DIM / 128, (N_TRIG + 127) / 128);
    gemm_mma_kernel<<<grid, 128, GSMEM>>>(out);
}

// round 9
// speedup vs baseline: 1.1525x; 1.0316x over previous
#include <cuda_runtime.h>
#include <cuda_bf16.h>
#include <cuda_fp16.h>
#include <cstdint>

// Problem constants
#define N_ENT    100000
#define N_REL    250000
#define N_TRIG   50000
#define N_ARGS   250000
#define ENT_DIM  288
#define REL_R    256
#define RTYPE_DIM 32
#define ROLE_DIM 256
#define ARG_DIM  576
#define KDIM     1152          // 2 * ARG_DIM (in-slot | out-slot)
#define OUT_COLS 544           // ENT_DIM + ROLE_DIM

// Scratch (fp16 X accumulators + fp16 W^T)
__device__ __half g_Xh[(size_t)N_TRIG * KDIM];   // 115.2 MB
__device__ __half g_Bth[ROLE_DIM * KDIM];        // W^T [n][k], fp16

// ---------------------------------------------------------------------------
// helpers
// ---------------------------------------------------------------------------
__device__ __forceinline__ uint32_t smem_u32(const void* p) {
    uint32_t a;
    asm("{ .reg .u64 t; cvta.to.shared.u64 t, %1; cvt.u32.u64 %0, t; }"
        : "=r"(a) : "l"(p));
    return a;
}

__device__ __forceinline__ void red_h8(__half* p, uint32_t a, uint32_t b,
                                       uint32_t c, uint32_t d) {
    asm volatile("red.global.add.noftz.v4.f16x2 [%0], {%1,%2,%3,%4};"
                 :: "l"(p), "r"(a), "r"(b), "r"(c), "r"(d) : "memory");
}

// streaming load (L2 evict_first) of a float4
__device__ __forceinline__ float4 ld4_stream(const float4* p, uint64_t pol) {
    float4 v;
    asm volatile("ld.global.nc.L2::cache_hint.v4.f32 {%0,%1,%2,%3}, [%4], %5;"
                 : "=f"(v.x), "=f"(v.y), "=f"(v.z), "=f"(v.w)
                 : "l"(p), "l"(pol));
    return v;
}

__device__ __forceinline__ void cp16(uint32_t dst, const void* src) {
    asm volatile("cp.async.cg.shared.global [%0], [%1], 16;" :: "r"(dst), "l"(src));
}
__device__ __forceinline__ void cp16_pred(uint32_t dst, const void* src, int bytes) {
    asm volatile("cp.async.cg.shared.global [%0], [%1], 16, %2;"
                 :: "r"(dst), "l"(src), "r"(bytes));
}
__device__ __forceinline__ void cp_commit() {
    asm volatile("cp.async.commit_group;" ::: "memory");
}
template <int N> __device__ __forceinline__ void cp_wait() {
    asm volatile("cp.async.wait_group %0;" :: "n"(N) : "memory");
}

#define MMA_F16(acc, ar, br)                                                    \
    asm volatile(                                                               \
        "mma.sync.aligned.m16n8k16.row.col.f32.f16.f16.f32 "                    \
        "{%0,%1,%2,%3},{%4,%5,%6,%7},{%8,%9},{%0,%1,%2,%3};"                    \
        : "+f"((acc)[0]), "+f"((acc)[1]), "+f"((acc)[2]), "+f"((acc)[3])        \
        : "r"((ar)[0]), "r"((ar)[1]), "r"((ar)[2]), "r"((ar)[3]),               \
          "r"((br)[0]), "r"((br)[1]))

#define LDMATRIX_X4(r, addr)                                                    \
    asm volatile("ldmatrix.sync.aligned.m8n8.x4.shared.b16 {%0,%1,%2,%3}, [%4];"\
                 : "=r"((r)[0]), "=r"((r)[1]), "=r"((r)[2]), "=r"((r)[3])       \
                 : "r"(addr))

// ---------------------------------------------------------------------------
// Fused prep kernel: [bprep | scatter | trig_copy] by block range.
// ---------------------------------------------------------------------------
#define PREP_BPREP 1152                     // (1152*256 elems)/256 thr
#define PREP_SCAT  (N_ARGS / 8)             // 31250, 1 arg per warp
#define PREP_TRIG  (N_TRIG / 8)             // 6250, 1 trig per warp
#define PREP_GRID  (PREP_BPREP + PREP_SCAT + PREP_TRIG)

__global__ __launch_bounds__(256)
void prep_kernel(const float* __restrict__ ent_embeds,
                 const float* __restrict__ rel_embeds,
                 const float* __restrict__ rtype_table,
                 const float* __restrict__ Win,
                 const float* __restrict__ Wout,
                 const int*   __restrict__ rtype_ids,
                 const int*   __restrict__ trig_ent_id,
                 const int*   __restrict__ arg_trig,
                 const int*   __restrict__ arg_rel,
                 const int*   __restrict__ arg_ent,
                 const int*   __restrict__ arg_is_in,
                 float* __restrict__ out) {
    int bid = blockIdx.x;
    int tid = threadIdx.x;
    int lane = tid & 31;
    int wip = tid >> 5;

    if (bid < PREP_BPREP) {
        int idx = bid * 256 + tid;
        int k = idx / ROLE_DIM;
        int n = idx % ROLE_DIM;
        float v = (k < ARG_DIM) ? Win[k * ROLE_DIM + n]
                                : Wout[(k - ARG_DIM) * ROLE_DIM + n];
        g_Bth[n * KDIM + k] = __float2half_rn(v);
        return;
    }
    bid -= PREP_BPREP;
    if (bid < PREP_SCAT) {
        int warp = bid * 8 + wip;
        int r = arg_rel[warp];
        int e = arg_ent[warp];
        int t = arg_trig[warp];
        int m = arg_is_in[warp];
        int rt = rtype_ids[r];

        // rel_embeds is a pure stream (each row used ~once): evict_first so it
        // doesn't thrash ent_embeds / X atomic sectors out of L2.
        uint64_t pol;
        asm("createpolicy.fractional.L2::evict_first.b64 %0, 1.0;" : "=l"(pol));

        const float4* relv = (const float4*)(rel_embeds  + (size_t)r  * REL_R);
        const float4* rtv  = (const float4*)(rtype_table + (size_t)rt * RTYPE_DIM);
        const float4* entv = (const float4*)(ent_embeds  + (size_t)e  * ENT_DIM);
        __half* base = g_Xh + (size_t)t * KDIM + (m ? 0 : ARG_DIM);

        #pragma unroll
        for (int it = 0; it < 3; ++it) {
            int c = lane + it * 32;          // 8-float chunk (0..71)
            if (c >= 72) break;
            float4 v0, v1;
            if (c < 32)       { v0 = ld4_stream(relv + c * 2, pol);
                                v1 = ld4_stream(relv + c * 2 + 1, pol); }
            else if (c < 36)  { v0 = rtv[(c - 32) * 2];  v1 = rtv[(c - 32) * 2 + 1]; }
            else              { v0 = entv[(c - 36) * 2]; v1 = entv[(c - 36) * 2 + 1]; }
            __half2 h0 = __floats2half2_rn(v0.x, v0.y);
            __half2 h1 = __floats2half2_rn(v0.z, v0.w);
            __half2 h2 = __floats2half2_rn(v1.x, v1.y);
            __half2 h3 = __floats2half2_rn(v1.z, v1.w);
            red_h8(base + c * 8, *(uint32_t*)&h0, *(uint32_t*)&h1,
                   *(uint32_t*)&h2, *(uint32_t*)&h3);
        }
        return;
    }
    bid -= PREP_SCAT;
    {
        int warp = bid * 8 + wip;
        const float4* src = (const float4*)(ent_embeds + (size_t)trig_ent_id[warp] * ENT_DIM);
        float4* dst = (float4*)(out + (size_t)warp * OUT_COLS);
        #pragma unroll
        for (int it = 0; it < 3; ++it) {
            int c = lane + it * 32;
            if (c < ENT_DIM / 4) dst[c] = src[c];
        }
    }
}

// ---------------------------------------------------------------------------
// mma.sync fp16 GEMM: out[:,288:544] = Xh[50000,1152] @ Wcat
// CTA: 128 threads (4 warps), tile 128m x 128n, warp tile 64x64.
// K-chunk 64, 3-stage cp.async pipeline, np-granular LDSM/MMA overlap.
// Rows padded to 144 B (conflict-free ldmatrix). grid n-major.
// ---------------------------------------------------------------------------
#define CHUNK  64
#define NCH    (KDIM / CHUNK)         // 18
#define ROWB   144
#define OFF_B  (128 * ROWB)           // 18432
#define STG_STRIDE (2 * 128 * ROWB)   // 36864
#define NSTAGE 3
#define GSMEM  (NSTAGE * STG_STRIDE)  // 110592

__global__ __launch_bounds__(128, 2)
void gemm_mma_kernel(float* __restrict__ out) {
    extern __shared__ char sm[];
    const uint32_t smb = smem_u32(sm);
    const int tid = threadIdx.x;
    const int lid = tid & 31;
    const int wid = tid >> 5;
    const int m0 = blockIdx.y * 128;
    const int n0 = blockIdx.x * 128;
    const int wm = (wid >> 1) * 64;        // warp m offset (0 or 64)
    const int wn = (wid & 1) * 64;         // warp n offset (0 or 64)
    const int g  = lid >> 2;               // 0..7
    const int kp = (lid & 3) * 2;          // 0,2,4,6

    float acc[4][8][4];                    // mf x nf x frag
    #pragma unroll
    for (int a = 0; a < 4; a++)
        #pragma unroll
        for (int b = 0; b < 8; b++)
            #pragma unroll
            for (int c = 0; c < 4; c++) acc[a][b][c] = 0.f;

    auto cpStage = [&](int c, int p) {
        uint32_t stg = smb + p * STG_STRIDE;
        #pragma unroll
        for (int u = 0; u < 8; u++) {
            int idx = u * 128 + tid;         // 0..1023
            int row = idx >> 3, seg = idx & 7;
            int gm = m0 + row;
            const __half* sa = g_Xh + (size_t)gm * KDIM + c * CHUNK + seg * 8;
            cp16_pred(stg + row * ROWB + seg * 16, sa, (gm < N_TRIG) ? 16 : 0);
            const __half* sb = g_Bth + (size_t)(n0 + row) * KDIM + c * CHUNK + seg * 8;
            cp16(stg + OFF_B + row * ROWB + seg * 16, sb);
        }
        cp_commit();
    };

    auto compute = [&](int p) {
        const uint32_t base = smb + p * STG_STRIDE;
        #pragma unroll
        for (int ks = 0; ks < 4; ks++) {
            uint32_t a[4][4], b[4][4];
            // earliest-needed loads first: b[0], then A; rest of B overlaps MMAs
            {
                uint32_t addr = base + OFF_B + (uint32_t)(wn + (lid & 15)) * ROWB
                              + ks * 32 + (lid >> 4) * 16;
                LDMATRIX_X4(b[0], addr);
            }
            #pragma unroll
            for (int mf = 0; mf < 4; mf++) {
                uint32_t addr = base + (uint32_t)(wm + mf * 16 + (lid & 15)) * ROWB
                              + ks * 32 + (lid >> 4) * 16;
                LDMATRIX_X4(a[mf], addr);
            }
            #pragma unroll
            for (int np = 0; np < 4; np++) {
                if (np < 3) {
                    uint32_t addr = base + OFF_B
                                  + (uint32_t)(wn + (np + 1) * 16 + (lid & 15)) * ROWB
                                  + ks * 32 + (lid >> 4) * 16;
                    LDMATRIX_X4(b[np + 1], addr);
                }
                uint32_t blo[2] = { b[np][0], b[np][2] };
                uint32_t bhi[2] = { b[np][1], b[np][3] };
                #pragma unroll
                for (int mf = 0; mf < 4; mf++) {
                    MMA_F16(acc[mf][2 * np],     a[mf], blo);
                    MMA_F16(acc[mf][2 * np + 1], a[mf], bhi);
                }
            }
        }
    };

    // ---- prologue: stages 0,1 in flight ----
    cpStage(0, 0);
    cpStage(1, 1);

    // ---- mainloop (single sync per iteration; 3 stages make the
    //      write target (i+2)%3 == (i-1)%3, protected by this sync) ----
    for (int i = 0; i < NCH; i++) {
        cp_wait<1>();
        __syncthreads();
        if (i + 2 < NCH) cpStage(i + 2, (i + 2) % NSTAGE);
        else             cp_commit();           // keep group count uniform
        compute(i % NSTAGE);
    }

    // ---- epilogue ----
    #pragma unroll
    for (int mf = 0; mf < 4; mf++) {
        int r = m0 + wm + mf * 16 + g;
        #pragma unroll
        for (int nf = 0; nf < 8; nf++) {
            int cc = ENT_DIM + n0 + wn + nf * 8 + kp;
            if (r < N_TRIG)
                *(float2*)(out + (size_t)r * OUT_COLS + cc) =
                    make_float2(acc[mf][nf][0], acc[mf][nf][1]);
            if (r + 8 < N_TRIG)
                *(float2*)(out + (size_t)(r + 8) * OUT_COLS + cc) =
                    make_float2(acc[mf][nf][2], acc[mf][nf][3]);
        }
    }
}

// ---------------------------------------------------------------------------
// Launch
// ---------------------------------------------------------------------------
extern "C" void kernel_launch(void* const* d_in, const int* in_sizes, int n_in,
                              void* d_out, int out_size) {
    const float* ent_embeds  = (const float*)d_in[0];
    const float* rel_embeds  = (const float*)d_in[1];
    const float* rtype_table = (const float*)d_in[2];
    const float* W_in        = (const float*)d_in[3];
    const float* W_out       = (const float*)d_in[4];
    const int*   rtype_ids   = (const int*)d_in[5];
    const int*   trig_ent_id = (const int*)d_in[6];
    const int*   arg_trig    = (const int*)d_in[7];
    const int*   arg_rel     = (const int*)d_in[8];
    const int*   arg_ent     = (const int*)d_in[9];
    const int*   arg_is_in   = (const int*)d_in[10];
    float* out = (float*)d_out;

    cudaFuncSetAttribute(gemm_mma_kernel,
                         cudaFuncAttributeMaxDynamicSharedMemorySize, GSMEM);

    // zero fp16 X accumulator (115 MB)
    void* xptr = nullptr;
    cudaGetSymbolAddress(&xptr, g_Xh);
    cudaMemsetAsync(xptr, 0, (size_t)N_TRIG * KDIM * sizeof(__half), 0);

    // fused: W transpose + scatter + trigger-embedding copy
    prep_kernel<<<PREP_GRID, 256>>>(ent_embeds, rel_embeds, rtype_table,
                                    W_in, W_out, rtype_ids, trig_ent_id,
                                    arg_trig, arg_rel, arg_ent, arg_is_in, out);

    // tensor-core GEMM -> out[:, 288:544]
    dim3 grid(ROLE_DIM / 128, (N_TRIG + 127) / 128);
    gemm_mma_kernel<<<grid, 128, GSMEM>>>(out);
}